// round 16
// baseline (speedup 1.0000x reference)
#include <cuda_runtime.h>
#include <cuda_bf16.h>
#include <cstdint>

// ContrastiveCosineLoss via signed feature-Gram SYRK on warp-level bf16 MMA.
// Round 16: paired-chunk bulk pipeline. Blocked g_Ys makes consecutive chunk
// slabs contiguous, so one cp.async.bulk fetches 128 samples (2 slabs).
// 4 barrier iterations per CTA (was 8), 2 stages, 3 CTAs/SM.
// Gram config otherwise = R15 (64x64 tiles, split-K=4, fused combine).

#define N_SAMPLES 2048
#define D_RED     128
#define D_TOT     1152                  // 18 * 64
#define TILE      64
#define NT        18
#define NTILES    171
#define NSPLIT    4
#define NCHUNK    32                    // total 64-sample chunks
#define NCHUNK_S  (NCHUNK / NSPLIT)     // 8 chunks per split
#define NPAIR     (NCHUNK_S / 2)        // 4 chunk-pairs per CTA
#define PITCHB    144                   // bytes per slab row (72 bf16, LDSM-safe)
#define SLABB     (64 * PITCHB)         // 9216 B per (tile,chunk) slab
#define PAIRB     (2 * SLABB)           // 18432 B per (tile,pair) bulk
#define STAGES    2
#define GSMEM     (STAGES * 2 * PAIRB)  // 73728 B dynamic smem (3 CTAs/SM)

__device__ __align__(4096) unsigned char g_Ys[NT * NCHUNK * SLABB]; // blocked bf16
__device__ __align__(4096) float g_G[NSPLIT * NTILES * TILE * TILE];
__device__ float g_part[NTILES];
__device__ unsigned int g_tile_count[NTILES];  // zero-init; self-resetting
__device__ unsigned int g_count;               // zero-init; self-resetting

// ---------------------------------------------------------------------------
__device__ __forceinline__ uint32_t smem_u32(const void* p) {
    uint32_t a;
    asm("{ .reg .u64 t; cvta.to.shared.u64 t, %1; cvt.u32.u64 %0, t; }" : "=r"(a) : "l"(p));
    return a;
}
__device__ __forceinline__ void mbar_init(uint32_t a, uint32_t cnt) {
    asm volatile("mbarrier.init.shared.b64 [%0], %1;" :: "r"(a), "r"(cnt) : "memory");
}
__device__ __forceinline__ void mbar_expect_tx(uint32_t a, uint32_t tx) {
    asm volatile("mbarrier.arrive.expect_tx.shared.b64 _, [%0], %1;"
                 :: "r"(a), "r"(tx) : "memory");
}
__device__ __forceinline__ void mbar_wait(uint32_t a, uint32_t parity) {
    asm volatile(
        "{\n\t.reg .pred P;\n\t"
        "WL_%=:\n\t"
        "mbarrier.try_wait.parity.acquire.cta.shared::cta.b64 P, [%0], %1, 0x989680;\n\t"
        "@!P bra WL_%=;\n\t}"
        :: "r"(a), "r"(parity) : "memory");
}
__device__ __forceinline__ void bulk_g2s(uint32_t sdst, const void* gsrc,
                                         uint32_t bytes, uint32_t mbar) {
    asm volatile(
        "cp.async.bulk.shared::cta.global.mbarrier::complete_tx::bytes "
        "[%0], [%1], %2, [%3];"
        :: "r"(sdst), "l"(gsrc), "r"(bytes), "r"(mbar) : "memory");
}
__device__ __forceinline__ void ldsm_x4_t(uint32_t* r, uint32_t addr) {
    asm volatile("ldmatrix.sync.aligned.m8n8.x4.trans.shared.b16 {%0,%1,%2,%3}, [%4];"
                 : "=r"(r[0]), "=r"(r[1]), "=r"(r[2]), "=r"(r[3]) : "r"(addr));
}
__device__ __forceinline__ void mma_bf16(float* c, const uint32_t* a, uint32_t b0, uint32_t b1) {
    asm volatile(
        "mma.sync.aligned.m16n8k16.row.col.f32.bf16.bf16.f32 "
        "{%0,%1,%2,%3}, {%4,%5,%6,%7}, {%8,%9}, {%0,%1,%2,%3};"
        : "+f"(c[0]), "+f"(c[1]), "+f"(c[2]), "+f"(c[3])
        : "r"(a[0]), "r"(a[1]), "r"(a[2]), "r"(a[3]), "r"(b0), "r"(b1));
}
__device__ __forceinline__ uint2 pack4_bf16(float x, float y, float z, float w) {
    __nv_bfloat162 h0 = __floats2bfloat162_rn(x, y);
    __nv_bfloat162 h1 = __floats2bfloat162_rn(z, w);
    return make_uint2(*(uint32_t*)&h0, *(uint32_t*)&h1);
}

// ---------------------------------------------------------------------------
// Kernel 1: row-normalize -> bf16, written DIRECTLY in the blocked slab
// layout: g_Ys[(tile*32 + chunk)*9216 + sample*144 + feat*2]. Warp per row.
// ---------------------------------------------------------------------------
__global__ void __launch_bounds__(256) normalize_kernel(const float* __restrict__ red,
                                                        const float* __restrict__ full) {
    int t = threadIdx.x, lane = t & 31, wid = t >> 5;
    int row = blockIdx.x * 8 + wid;

    const float4* f4 = (const float4*)(full + (size_t)row * 1024);
    const float4* r4 = (const float4*)(red  + (size_t)row * D_RED);

    float4 fv[8];
    #pragma unroll
    for (int j = 0; j < 8; j++) fv[j] = f4[lane + 32 * j];
    float4 rv = r4[lane];

    float sf = 0.f;
    #pragma unroll
    for (int j = 0; j < 8; j++)
        sf += fv[j].x * fv[j].x + fv[j].y * fv[j].y + fv[j].z * fv[j].z + fv[j].w * fv[j].w;
    float sr = rv.x * rv.x + rv.y * rv.y + rv.z * rv.z + rv.w * rv.w;

    #pragma unroll
    for (int o = 16; o > 0; o >>= 1) {
        sf += __shfl_xor_sync(0xFFFFFFFFu, sf, o);
        sr += __shfl_xor_sync(0xFFFFFFFFu, sr, o);
    }
    float iff = 1.f / fmaxf(sqrtf(sf), 1e-8f);
    float ir  = 1.f / fmaxf(sqrtf(sr), 1e-8f);

    int c = row >> 6, s = row & 63;
    size_t rowOff = (size_t)c * SLABB + (size_t)s * PITCHB + (lane & 15) * 8;
    const size_t tileStride = (size_t)NCHUNK * SLABB;

    {   // reduced block -> tiles 0,1
        int tile = lane >> 4;
        *(uint2*)(g_Ys + tile * tileStride + rowOff) =
            pack4_bf16(rv.x * ir, rv.y * ir, rv.z * ir, rv.w * ir);
    }
    #pragma unroll
    for (int j = 0; j < 8; j++) {   // full block -> tiles 2..17
        int tile = 2 + j * 2 + (lane >> 4);
        *(uint2*)(g_Ys + tile * tileStride + rowOff) =
            pack4_bf16(fv[j].x * iff, fv[j].y * iff, fv[j].z * iff, fv[j].w * iff);
    }
}

// ---------------------------------------------------------------------------
// Kernel 2: bf16 warp-MMA partial SYRK (split-K=4), paired-chunk bulk
// pipeline (4 iterations), decoupled per-tile combine + global finalize.
// grid = (NTILES, NSPLIT), 256 threads, 8 warps = 2x2 quadrants x 2 k-halves.
// ---------------------------------------------------------------------------
__global__ void __launch_bounds__(256, 3) gram_kernel(float* __restrict__ out) {
    extern __shared__ __align__(16) char dyn[];
    __shared__ __align__(8) unsigned long long s_mbar[STAGES];
    __shared__ float sred[8];
    __shared__ unsigned int s_comb, s_last;

    int t = threadIdx.x, lane = t & 31, wid = t >> 5;

    int blk = blockIdx.x, split = blockIdx.y;
    int a = 0, rem = blk, rl = NT;
    while (rem >= rl) { rem -= rl; a++; rl--; }
    int b2 = a + rem;

    const uint32_t sbase = smem_u32(dyn);
    const unsigned char* gA = g_Ys + ((size_t)a  * NCHUNK + split * NCHUNK_S) * SLABB;
    const unsigned char* gB = g_Ys + ((size_t)b2 * NCHUNK + split * NCHUNK_S) * SLABB;

    uint32_t mb[STAGES];
    #pragma unroll
    for (int s = 0; s < STAGES; s++) mb[s] = smem_u32(&s_mbar[s]);

    if (t == 0) {
        #pragma unroll
        for (int s = 0; s < STAGES; s++) mbar_init(mb[s], 1);
    }
    __syncthreads();

    auto issue = [&](int s, int p) {   // t==0 only; one pair = 2 chunks
        uint32_t dst = sbase + (uint32_t)(s * 2 * PAIRB);
        mbar_expect_tx(mb[s], 2 * PAIRB);
        bulk_g2s(dst,         gA + (size_t)p * PAIRB, PAIRB, mb[s]);
        bulk_g2s(dst + PAIRB, gB + (size_t)p * PAIRB, PAIRB, mb[s]);
    };

    if (t == 0) { issue(0, 0); issue(1, 1); }

    // ---- warp tiling: 2x2 quadrants x 2 k-halves ----
    int wq = wid & 3, kh = wid >> 2;
    int m0 = (wq & 1) * 32;
    int n0 = (wq >> 1) * 32;
    int lrow = (lane & 7) + ((lane >> 4) & 1) * 8;
    int lcol = ((lane >> 3) & 1) * 8;
    const uint32_t offA = (uint32_t)((kh * 32 + lrow) * PITCHB + (m0 + lcol) * 2);
    const uint32_t offB = (uint32_t)(PAIRB + (kh * 32 + lrow) * PITCHB + (n0 + lcol) * 2);
    const uint32_t kStep = 16 * PITCHB;

    float acc[2][4][4] = {};

    for (int p = 0; p < NPAIR; p++) {
        int s = p & 1;
        int parity = (p >> 1) & 1;
        mbar_wait(mb[s], parity);
        __syncthreads();

        uint32_t so = sbase + (uint32_t)(s * 2 * PAIRB);
        #pragma unroll
        for (int sub = 0; sub < 2; sub++) {      // two 64-sample sub-chunks
            uint32_t aA = so + sub * SLABB + offA;
            uint32_t aB = so + sub * SLABB + offB;
            uint32_t af[2][2][4], bf[2][2][4];
            #pragma unroll
            for (int ks = 0; ks < 2; ks++) {
                uint32_t ko = ks * kStep;
                ldsm_x4_t(af[ks][0], aA + ko);
                ldsm_x4_t(af[ks][1], aA + ko + 32);
                ldsm_x4_t(bf[ks][0], aB + ko);
                ldsm_x4_t(bf[ks][1], aB + ko + 32);
            }
            #pragma unroll
            for (int ks = 0; ks < 2; ks++)
                #pragma unroll
                for (int mi = 0; mi < 2; mi++) {
                    mma_bf16(acc[mi][0], af[ks][mi], bf[ks][0][0], bf[ks][0][2]);
                    mma_bf16(acc[mi][1], af[ks][mi], bf[ks][0][1], bf[ks][0][3]);
                    mma_bf16(acc[mi][2], af[ks][mi], bf[ks][1][0], bf[ks][1][2]);
                    mma_bf16(acc[mi][3], af[ks][mi], bf[ks][1][1], bf[ks][1][3]);
                }
        }

        __syncthreads();                 // all warps done reading stage s
        if (t == 0 && p + 2 < NPAIR) issue(s, p + 2);
    }

    // ---- merge k-halves via SMEM, write partial Gram ----
    __syncthreads();
    float4* M4 = (float4*)dyn;
    int tt = wq * 32 + lane;
    if (kh == 1) {
        #pragma unroll
        for (int mi = 0; mi < 2; mi++)
            #pragma unroll
            for (int ni = 0; ni < 4; ni++)
                M4[(mi * 4 + ni) * 128 + tt] =
                    make_float4(acc[mi][ni][0], acc[mi][ni][1],
                                acc[mi][ni][2], acc[mi][ni][3]);
    }
    __syncthreads();
    if (kh == 0) {
        float4* G4 = (float4*)g_G + ((size_t)(split * NTILES + blk)) * 1024;
        #pragma unroll
        for (int mi = 0; mi < 2; mi++)
            #pragma unroll
            for (int ni = 0; ni < 4; ni++) {
                int f = mi * 4 + ni;
                float4 v = M4[f * 128 + tt];
                G4[f * 128 + tt] = make_float4(acc[mi][ni][0] + v.x,
                                               acc[mi][ni][1] + v.y,
                                               acc[mi][ni][2] + v.z,
                                               acc[mi][ni][3] + v.w);
            }
    }

    // ---- decoupled per-tile combine (threadFenceReduction pattern) ----
    __syncthreads();
    if (t == 0) {
        __threadfence();
        s_comb = (atomicAdd(&g_tile_count[blk], 1u) == NSPLIT - 1);
    }
    __syncthreads();
    if (!s_comb) return;

    __threadfence();   // acquire partials written by sibling CTAs
    {
        const float4* G4 = (const float4*)g_G;
        float sum = 0.f;
        #pragma unroll
        for (int f = 0; f < 4; f++) {
            size_t idx = (size_t)blk * 1024 + f * 256 + t;
            float x = 0.f, y = 0.f, z = 0.f, w = 0.f;
            #pragma unroll
            for (int sp = 0; sp < NSPLIT; sp++) {   // fixed order: deterministic
                float4 u = G4[(size_t)sp * NTILES * 1024 + idx];
                x += u.x; y += u.y; z += u.z; w += u.w;
            }
            sum += x * x + y * y + z * z + w * w;
        }
        #pragma unroll
        for (int o = 16; o > 0; o >>= 1)
            sum += __shfl_xor_sync(0xFFFFFFFFu, sum, o);
        if (lane == 0) sred[wid] = sum;
    }
    __syncthreads();
    if (t == 0) {
        float tot = 0.f;
        #pragma unroll
        for (int i = 0; i < 8; i++) tot += sred[i];
        float sp = ((a < 2) != (b2 < 2)) ? -1.f : 1.f;
        float w  = sp * ((a == b2) ? 1.f : 2.f);
        g_part[blk] = w * tot;
        g_tile_count[blk] = 0;     // reset for next graph replay
        __threadfence();
        s_last = (atomicAdd(&g_count, 1u) == NTILES - 1);
    }
    __syncthreads();

    // ---- global finalize by last tile-combiner ----
    if (s_last) {
        __threadfence();
        __shared__ float fs[256];
        fs[t] = (t < NTILES) ? g_part[t] : 0.f;
        __syncthreads();
        #pragma unroll
        for (int o = 128; o > 0; o >>= 1) {
            if (t < o) fs[t] += fs[t + o];
            __syncthreads();
        }
        if (t == 0) {
            out[0] = fs[0] / ((float)N_SAMPLES * (float)(N_SAMPLES - 1));
            g_count = 0;           // reset for next graph replay
        }
    }
}

// ---------------------------------------------------------------------------
extern "C" void kernel_launch(void* const* d_in, const int* in_sizes, int n_in,
                              void* d_out, int out_size) {
    const float* red;
    const float* full;
    if (in_sizes[0] == N_SAMPLES * D_RED) {
        red  = (const float*)d_in[0];
        full = (const float*)d_in[1];
    } else {
        red  = (const float*)d_in[1];
        full = (const float*)d_in[0];
    }

    static int attr_done = 0;
    if (!attr_done) {
        cudaFuncSetAttribute(gram_kernel, cudaFuncAttributeMaxDynamicSharedMemorySize,
                             GSMEM);
        attr_done = 1;
    }

    normalize_kernel<<<N_SAMPLES / 8, 256>>>(red, full);
    gram_kernel<<<dim3(NTILES, NSPLIT), 256, GSMEM>>>((float*)d_out);
}